// round 1
// baseline (speedup 1.0000x reference)
#include <cuda_runtime.h>

#define NUM 16
#define DIM 128
#define NN (NUM*DIM)            // 2048
#define BATCH 4096
#define INC 512
#define OUTC 512
#define STEPS 10

// ---------------- device scratch (no runtime alloc allowed) ----------------
__device__ __align__(16) float g_R[2][NN*DIM];         // backward state T^k[:, block15]
__device__ __align__(16) float g_S[NN*DIM];            // sum of R_0..R_9
__device__ __align__(16) float g_P[NUM*NUM*DIM*DIM];   // split-K partials (16 MB)
__device__ __align__(16) float g_beta[NN];             // per-step constant bias (flat)
__device__ __align__(16) float g_h[DIM];
__device__ __align__(16) float g_WpostT[DIM*OUTC];
__device__ __align__(16) float g_T1[DIM*OUTC];
__device__ __align__(16) float g_G[INC*OUTC];
__device__ __align__(16) float g_dvec[OUTC];

// packed 2x fp32 FMA (sm_100+): c.lo += a.lo*b.lo ; c.hi += a.hi*b.hi
__device__ __forceinline__ void fma2(unsigned long long& c, unsigned long long a,
                                     unsigned long long b) {
    asm("fma.rn.f32x2 %0, %1, %2, %0;" : "+l"(c) : "l"(a), "l"(b));
}

// ---------------- small prep kernels ----------------

// beta[j*128+g] = sum_i gate[i,j] * b[i,j,g]
__global__ void k_prep(const float* __restrict__ life, const float* __restrict__ bl) {
    int j = blockIdx.x, g = threadIdx.x;
    float s = 0.f;
#pragma unroll
    for (int i = 0; i < NUM; i++) {
        float gt = fmaxf(life[i*NUM + j], 0.f);
        s += gt * bl[(i*NUM + j)*DIM + g];
    }
    g_beta[j*DIM + g] = s;
}

// R_0 = identity columns of block 15 ; S = R_0
__global__ void k_init() {
    int row = blockIdx.x, e = threadIdx.x;
    float v = (row >= (NUM-1)*DIM && (row - (NUM-1)*DIM) == e) ? 1.f : 0.f;
    g_R[0][row*DIM + e] = v;
    g_S[row*DIM + e]    = v;
}

// WpostT[e][q] = Wpost[q][e]
__global__ void k_transpose(const float* __restrict__ Wpost) {
    int e = blockIdx.x, q = threadIdx.x;
    g_WpostT[e*OUTC + q] = Wpost[q*DIM + e];
}

// ---------------- backward step: partial GEMMs ----------------
// block (i,j): P[i][j][f][e] = gate[i,j] * sum_g W[i,j,g,f] * R[(j,g), e]
__global__ __launch_bounds__(256, 2) void k_step(const float* __restrict__ W,
                                                 const float* __restrict__ life,
                                                 int cur) {
    const int i = blockIdx.y, j = blockIdx.x;
    const float gate = fmaxf(life[i*NUM + j], 0.f);
    const float* __restrict__ A  = W + (i*NUM + j)*DIM*DIM;   // [g][f], f contiguous
    const float* __restrict__ Bm = g_R[cur] + j*DIM*DIM;      // [g][e], e contiguous
    float* __restrict__ Pout = g_P + (i*NUM + j)*DIM*DIM;

    __shared__ float2 Asd[16][DIM + 1];                  // dup pairs (a,a), padded
    __shared__ __align__(16) float Bs[16][DIM];

    const int tid = threadIdx.x;
    const int tx = tid & 15, ty = tid >> 4;

    unsigned long long acc[8][4];
#pragma unroll
    for (int u = 0; u < 8; u++)
#pragma unroll
        for (int v = 0; v < 4; v++) acc[u][v] = 0ull;

    for (int g0 = 0; g0 < DIM; g0 += 16) {
        const float2* Ag = (const float2*)(A  + g0*DIM);
        const float2* Bg = (const float2*)(Bm + g0*DIM);
#pragma unroll
        for (int c = 0; c < 4; c++) {
            int idx = c*256 + tid;              // float2 index, 1024 total
            int g = idx >> 6, f2 = idx & 63;
            float2 av = Ag[idx];
            float2 bv = Bg[idx];
            Asd[g][2*f2]     = make_float2(av.x, av.x);
            Asd[g][2*f2 + 1] = make_float2(av.y, av.y);
            *(float2*)&Bs[g][2*f2] = bv;
        }
        __syncthreads();
#pragma unroll
        for (int kk = 0; kk < 16; kk++) {
            unsigned long long a[8], b[4];
#pragma unroll
            for (int u = 0; u < 8; u++)
                a[u] = *(const unsigned long long*)&Asd[kk][u*16 + ty];
#pragma unroll
            for (int v = 0; v < 4; v++)
                b[v] = *(const unsigned long long*)&Bs[kk][2*tx + v*32];
#pragma unroll
            for (int u = 0; u < 8; u++)
#pragma unroll
                for (int v = 0; v < 4; v++)
                    fma2(acc[u][v], a[u], b[v]);
        }
        __syncthreads();
    }
#pragma unroll
    for (int u = 0; u < 8; u++) {
        int f = u*16 + ty;
#pragma unroll
        for (int v = 0; v < 4; v++) {
            int e = 2*tx + v*32;
            union { unsigned long long u64; float2 f2; } cv;
            cv.u64 = acc[u][v];
            float2 o = make_float2(gate*cv.f2.x, gate*cv.f2.y);
            *(float2*)&Pout[f*DIM + e] = o;
        }
    }
}

// Rnext[(i,f),e] = sum_j P[i][j][f][e] ; optionally S += Rnext
__global__ void k_reduce(int cur, int addS) {
    int row = blockIdx.x, e = threadIdx.x;
    int i = row >> 7, f = row & 127;
    float s = 0.f;
#pragma unroll
    for (int j = 0; j < NUM; j++)
        s += g_P[(i*NUM + j)*DIM*DIM + f*DIM + e];
    g_R[cur ^ 1][row*DIM + e] = s;
    if (addS) g_S[row*DIM + e] += s;
}

// ---------------- combine kernels ----------------

// h[e] = sum_d bpre[d]*E[d,e] + sum_r beta[r]*S[r,e]   (E = rows 0..127 of R_10)
__global__ void k_h(const float* __restrict__ bpre, int fin) {
    int e = blockIdx.x;
    int tid = threadIdx.x;
    float s = 0.f;
    for (int r = tid; r < NN; r += 256) s += g_beta[r] * g_S[r*DIM + e];
    if (tid < DIM) s += bpre[tid] * g_R[fin][tid*DIM + e];
    __shared__ float red[256];
    red[tid] = s;
    __syncthreads();
    for (int off = 128; off > 0; off >>= 1) {
        if (tid < off) red[tid] += red[tid + off];
        __syncthreads();
    }
    if (tid == 0) g_h[e] = red[0];
}

// T1[d][q] = sum_e E[d][e] * WpostT[e][q]
__global__ void k_T1(int fin) {
    int d = blockIdx.y;
    int q = blockIdx.x*128 + threadIdx.x;
    const float* __restrict__ Er = g_R[fin] + d*DIM;
    float acc = 0.f;
#pragma unroll 8
    for (int e = 0; e < DIM; e++)
        acc += Er[e] * g_WpostT[e*OUTC + q];
    g_T1[d*OUTC + q] = acc;
}

// G[p][q] = sum_d Wpre[d][p] * T1[d][q]
__global__ void k_G(const float* __restrict__ Wpre) {
    int p = blockIdx.y;
    int q = blockIdx.x*128 + threadIdx.x;
    float acc = 0.f;
#pragma unroll 8
    for (int d = 0; d < DIM; d++)
        acc += Wpre[d*INC + p] * g_T1[d*OUTC + q];
    g_G[p*OUTC + q] = acc;
}

// dvec[q] = sum_e h[e]*WpostT[e][q] + bpost[q]
__global__ void k_dvec(const float* __restrict__ bpost) {
    int q = blockIdx.x*128 + threadIdx.x;
    float acc = bpost[q];
#pragma unroll 8
    for (int e = 0; e < DIM; e++)
        acc += g_h[e] * g_WpostT[e*OUTC + q];
    g_dvec[q] = acc;
}

// ---------------- final GEMM: out = inp @ G + dvec ----------------
__global__ __launch_bounds__(256, 2) void k_final(const float* __restrict__ inp,
                                                  float* __restrict__ out) {
    const int q0 = blockIdx.x * 128;
    const int b0 = blockIdx.y * 128;

    __shared__ float2 Asd[16][DIM + 1];
    __shared__ __align__(16) float Bs[16][DIM];

    const int tid = threadIdx.x;
    const int tx = tid & 15, ty = tid >> 4;

    unsigned long long acc[8][4];
#pragma unroll
    for (int u = 0; u < 8; u++)
#pragma unroll
        for (int v = 0; v < 4; v++) acc[u][v] = 0ull;

    for (int p0 = 0; p0 < INC; p0 += 16) {
        // A chunk: inp[b0..+127][p0..+15]  (transpose into Asd[pp][bb], duplicated)
#pragma unroll
        for (int c = 0; c < 4; c++) {
            int idx = c*256 + tid;          // 1024 float2
            int bb = idx >> 3, p2 = idx & 7;
            float2 av = *(const float2*)&inp[(b0 + bb)*INC + p0 + 2*p2];
            Asd[2*p2][bb]     = make_float2(av.x, av.x);
            Asd[2*p2 + 1][bb] = make_float2(av.y, av.y);
        }
        // B chunk: G[p0..+15][q0..+127]
#pragma unroll
        for (int c = 0; c < 4; c++) {
            int idx = c*256 + tid;
            int pp = idx >> 6, q2 = idx & 63;
            float2 bv = *(const float2*)&g_G[(p0 + pp)*OUTC + q0 + 2*q2];
            *(float2*)&Bs[pp][2*q2] = bv;
        }
        __syncthreads();
#pragma unroll
        for (int kk = 0; kk < 16; kk++) {
            unsigned long long a[8], b[4];
#pragma unroll
            for (int u = 0; u < 8; u++)
                a[u] = *(const unsigned long long*)&Asd[kk][u*16 + ty];
#pragma unroll
            for (int v = 0; v < 4; v++)
                b[v] = *(const unsigned long long*)&Bs[kk][2*tx + v*32];
#pragma unroll
            for (int u = 0; u < 8; u++)
#pragma unroll
                for (int v = 0; v < 4; v++)
                    fma2(acc[u][v], a[u], b[v]);
        }
        __syncthreads();
    }
#pragma unroll
    for (int u = 0; u < 8; u++) {
        int bb = u*16 + ty;
#pragma unroll
        for (int v = 0; v < 4; v++) {
            int e = 2*tx + v*32;
            union { unsigned long long u64; float2 f2; } cv;
            cv.u64 = acc[u][v];
            float2 dv = *(const float2*)&g_dvec[q0 + e];
            float2 o = make_float2(cv.f2.x + dv.x, cv.f2.y + dv.y);
            *(float2*)&out[(b0 + bb)*OUTC + q0 + e] = o;
        }
    }
}

// ---------------- launch ----------------
extern "C" void kernel_launch(void* const* d_in, const int* in_sizes, int n_in,
                              void* d_out, int out_size) {
    (void)in_sizes; (void)n_in; (void)out_size;
    const float* inp   = (const float*)d_in[0];
    const float* Wpre  = (const float*)d_in[1];
    const float* bpre  = (const float*)d_in[2];
    const float* W     = (const float*)d_in[3];
    const float* bl    = (const float*)d_in[4];
    const float* life  = (const float*)d_in[5];
    const float* Wpost = (const float*)d_in[6];
    const float* bpost = (const float*)d_in[7];
    float* out = (float*)d_out;

    k_prep<<<NUM, DIM>>>(life, bl);
    k_init<<<NN, DIM>>>();
    k_transpose<<<DIM, OUTC>>>(Wpost);

    int cur = 0;
    for (int s = 0; s < STEPS; s++) {
        k_step<<<dim3(NUM, NUM), 256>>>(W, life, cur);
        k_reduce<<<NN, DIM>>>(cur, (s < STEPS - 1) ? 1 : 0);
        cur ^= 1;
    }
    // after 10 steps, R_10 lives in g_R[cur] (cur == 0)
    k_h<<<DIM, 256>>>(bpre, cur);
    k_T1<<<dim3(OUTC/128, DIM), 128>>>(cur);
    k_G<<<dim3(OUTC/128, INC), 128>>>(Wpre);
    k_dvec<<<OUTC/128, 128>>>(bpost);
    k_final<<<dim3(OUTC/128, BATCH/128), 256>>>(inp, out);
}